// round 5
// baseline (speedup 1.0000x reference)
#include <cuda_runtime.h>
#include <cstdint>

// Problem dims (fixed by the dataset's setup_inputs)
#define C_   128
#define H_   56
#define W_   56
#define HW_  3136
#define TOTAL_ (16 * 128 * 3136)

#define NPAIR_BC  1568                    // HW/2 pixel-pairs per (b,c)
#define NPAIR_TOT (16 * 128 * NPAIR_BC)   // 3,211,264
#define TPB 256

// set.ge -> -1 (true) / 0 (false): single SASS FSET, no predication
__device__ __forceinline__ int setge(float a, float b) {
    int r;
    asm("set.ge.s32.f32 %0, %1, %2;" : "=r"(r) : "f"(a), "f"(b));
    return r;
}

__global__ __launch_bounds__(TPB, 6)   // cap regs at 40 -> 48 warps/SM
void rrsvm_kernel(const float* __restrict__ x,
                  const float* __restrict__ s,
                  float* __restrict__ vout,
                  float* __restrict__ idxout)
{
    __shared__ float ssm[8][9];                       // per-warp rank weights
    __shared__ __align__(16) float stage[8][576];     // per-warp idx staging

    const int tid  = threadIdx.x;
    const int warp = tid >> 5;
    const int lane = tid & 31;
    const int t    = blockIdx.x * TPB + tid;          // pair id, exact grid

    const int bc = t / NPAIR_BC;                      // b*C + c
    const int q  = t - bc * NPAIR_BC;
    const int y  = q / 28;                            // output row
    const int xx = (q - y * 28) * 2;                  // left pixel col (even)

    // warp never straddles (b,c): NPAIR_BC = 1568 is a multiple of 32
    if (lane < 9)
        ssm[warp][lane] = __ldg(s + (bc & (C_ - 1)) * 9 + lane);
    __syncwarp();

    const float* __restrict__ xb = x + (size_t)bc * HW_;

    // 3 rows x 4 cols covering both 3x3 windows (zero padding = real values).
    // Middle pair is an aligned float2 (xx even); only edges are scalar.
    float v[3][4];
#pragma unroll
    for (int rr = 0; rr < 3; rr++) {
        const int gy   = y + rr - 1;
        const bool rok = ((unsigned)gy < (unsigned)H_);
        const float* p = xb + gy * W_ + xx;
        float2 mid = make_float2(0.f, 0.f);
        if (rok) mid = *(const float2*)p;             // 8B aligned
        v[rr][1] = mid.x;
        v[rr][2] = mid.y;
        v[rr][0] = (rok & (xx > 0))  ? __ldg(p - 1) : 0.f;
        v[rr][3] = (rok & (xx < 54)) ? __ldg(p + 2) : 0.f;
    }

    // Stable-descending ranks for both windows, accumulated directly from
    // signed masks (m = -1 when earlier-index element wins; ties -> earlier
    // index, matching stable jnp.argsort(-p)). Masks die immediately.
    int r0[9], r1[9];
#pragma unroll
    for (int e = 0; e < 9; e++) { r0[e] = 8 - e; r1[e] = 8 - e; }

    // within-row pairs (a<b), skip unused (0,3)
#pragma unroll
    for (int rr = 0; rr < 3; rr++) {
#pragma unroll
        for (int a = 0; a < 4; a++) {
#pragma unroll
            for (int b = a + 1; b < 4; b++) {
                if (a == 0 && b == 3) continue;
                const int m = setge(v[rr][a], v[rr][b]);
                if (b <= 2) { r0[rr*3 + a]     += m; r0[rr*3 + b]     -= m; }
                if (a >= 1) { r1[rr*3 + a - 1] += m; r1[rr*3 + b - 1] -= m; }
            }
        }
    }
    // cross-row pairs: row pairs (0,1),(0,2),(1,2), all col combos except (0,3),(3,0)
#pragma unroll
    for (int rp = 0; rp < 3; rp++) {
        const int ra = (rp < 2) ? 0 : 1;
        const int rb = (rp == 0) ? 1 : 2;
#pragma unroll
        for (int a = 0; a < 4; a++) {
#pragma unroll
            for (int b = 0; b < 4; b++) {
                if ((a == 0 && b == 3) || (a == 3 && b == 0)) continue;
                const int m = setge(v[ra][a], v[rb][b]);   // (ra,·) earlier index
                if (a <= 2 && b <= 2) { r0[ra*3 + a]     += m; r0[rb*3 + b]     -= m; }
                if (a >= 1 && b >= 1) { r1[ra*3 + a - 1] += m; r1[rb*3 + b - 1] -= m; }
            }
        }
    }

    // Values (gather s via conflict-free LDS) + index scatter into warp stage
    float acc0 = 0.f, acc1 = 0.f;
    float* st = &stage[warp][lane * 18];
#pragma unroll
    for (int e = 0; e < 9; e++) {
        acc0 = fmaf(v[e/3][e%3],     ssm[warp][r0[e]], acc0);
        acc1 = fmaf(v[e/3][e%3 + 1], ssm[warp][r1[e]], acc1);
        st[r0[e]]     = (float)e;    // constant payload, no I2F
        st[9 + r1[e]] = (float)e;
    }

    if (vout) {
        float2 o = make_float2(acc0, acc1);
        __stcs((float2*)(vout + (size_t)bc * HW_ + y * W_ + xx), o);  // 8B aligned
    }

    __syncwarp();
    if (idxout) {
        // warp's 64 pixels own a contiguous 576-float (144 float4) span
        const float4* sf  = (const float4*)stage[warp];
        float4*       dst = (float4*)(idxout + (size_t)(t - lane) * 18);
#pragma unroll
        for (int k = 0; k < 4; k++)
            __stcs(dst + lane + 32 * k, sf[lane + 32 * k]);
        if (lane < 16)
            __stcs(dst + lane + 128, sf[lane + 128]);
    }
}

extern "C" void kernel_launch(void* const* d_in, const int* in_sizes, int n_in,
                              void* d_out, int out_size) {
    const float* x = (const float*)d_in[0];
    const float* s = (const float*)d_in[1];

    float* vout   = (float*)d_out;
    float* idxout = nullptr;

    // Reference returns (out[B,C,H,W], indices[B,C,H,W,9]); harness concatenates.
    if (out_size >= 10 * TOTAL_) {
        idxout = (float*)d_out + TOTAL_;   // [out | indices]
    } else if (out_size == 9 * TOTAL_) {
        idxout = (float*)d_out;            // indices only
        vout   = nullptr;
    }

    const int blocks = NPAIR_TOT / TPB;    // exact: 12544
    rrsvm_kernel<<<blocks, TPB>>>(x, s, vout, idxout);
}